// round 17
// baseline (speedup 1.0000x reference)
#include <cuda_runtime.h>
#include <cuda_bf16.h>
#include <math.h>
#include <stdint.h>

// Problem constants
#define BB 4
#define SS 2048
#define DD 1024
#define MS (BB*SS)          // 8192 rows

#define KC  64              // K bf16 elements per chunk (= 128B smem rows)
#define SM_BUF 16384        // one 128x64 bf16 tile
#define NSTAGE 3
#define SM_STAGE (2*SM_BUF)
#define SM_TOTAL (NSTAGE*SM_STAGE)   // 96 KB

#define EXP_BIAS 6.0f       // fixed softmax shift (logit sigma ~0.33, max ~1.2)

// Scratch (no allocations allowed -> device globals)
__device__ __nv_bfloat16 g_cls_bf[MS*DD];            // 16 MB
__device__ __nv_bfloat16 g_q_bf[MS*DD];              // 16 MB
__device__ __nv_bfloat16 g_Wc_bf[DD*DD];             // 2 MB
__device__ __nv_bfloat16 g_Wq_bf[DD*DD];             // 2 MB
__device__ __nv_bfloat16 g_Wg_bf[DD*2*DD];           // 4 MB
__device__ __nv_bfloat16 g_cproj[MS*DD];             // 16 MB
__device__ __nv_bfloat16 g_qproj[MS*DD];             // 16 MB
__device__ __nv_bfloat16 g_qT[(size_t)BB*DD*SS];     // 16 MB
__device__ __nv_bfloat16 g_attn[(size_t)BB*SS*SS];   // 32 MB (unnormalized exp)
__device__ float g_iface[MS*DD];                     // 32 MB
__device__ float g_rowsum[MS];                       // 32 KB

// ---------------------------------------------------------------------------
__device__ __forceinline__ uint32_t smem_u32(const void* p) {
    uint32_t a;
    asm("{ .reg .u64 t; cvta.to.shared.u64 t, %1; cvt.u32.u64 %0, t; }" : "=r"(a) : "l"(p));
    return a;
}
__device__ __forceinline__ uint32_t pack_bf16(float lo, float hi) {
    uint32_t u;
    asm("cvt.rn.bf16x2.f32 %0, %1, %2;" : "=r"(u) : "f"(hi), "f"(lo));
    return u;
}

#define CP_COMMIT() asm volatile("cp.async.commit_group;" ::: "memory")
#define CP_WAIT(n)  asm volatile("cp.async.wait_group %0;" :: "n"(n) : "memory")

#define LDSM4(d, addr) \
    asm volatile("ldmatrix.sync.aligned.m8n8.x4.shared.b16 {%0,%1,%2,%3}, [%4];" \
        : "=r"((d)[0]), "=r"((d)[1]), "=r"((d)[2]), "=r"((d)[3]) : "r"(addr))

__device__ __forceinline__ void mma16(float* c, const uint32_t* a, const uint32_t* b) {
    asm volatile("mma.sync.aligned.m16n8k16.row.col.f32.bf16.bf16.f32 "
                 "{%0,%1,%2,%3}, {%4,%5,%6,%7}, {%8,%9}, {%0,%1,%2,%3};"
                 : "+f"(c[0]), "+f"(c[1]), "+f"(c[2]), "+f"(c[3])
                 : "r"(a[0]), "r"(a[1]), "r"(a[2]), "r"(a[3]), "r"(b[0]), "r"(b[1]));
}

// Issue one chunk's A+B loads (8 cp.async per thread @256 threads), 1 commit.
__device__ __forceinline__ void issue_chunk(const __nv_bfloat16* __restrict__ baseA,
                                            const __nv_bfloat16* __restrict__ baseB,
                                            const int* rowoffA, const int* rowoffB,
                                            const uint32_t* smoff, uint32_t stg) {
    #pragma unroll
    for (int i = 0; i < 4; i++)
        asm volatile("cp.async.cg.shared.global [%0], [%1], 16;"
            :: "r"(stg + smoff[i]), "l"(baseA + rowoffA[i]));
    #pragma unroll
    for (int i = 0; i < 4; i++)
        asm volatile("cp.async.cg.shared.global [%0], [%1], 16;"
            :: "r"(stg + SM_BUF + smoff[i]), "l"(baseB + rowoffB[i]));
    CP_COMMIT();
}

// ---------------------------------------------------------------------------
struct GemmCtx {
    int tid, wid, lane, g, tig, mw, nw;
    int rowoffA[4], rowoffB[4];
    uint32_t smoff[4];
    uint32_t segoff[4];
    uint32_t ArowB, BrowB;
};

__device__ __forceinline__ void gemm_setup(GemmCtx& cx, uint32_t sb,
                                           int row0, int col0, int lda, int ldb) {
    int tid  = threadIdx.x;
    cx.tid = tid;
    cx.wid  = tid >> 5;
    cx.lane = tid & 31;
    cx.g    = cx.lane >> 2;
    cx.tig  = cx.lane & 3;
    cx.mw   = (cx.wid >> 2) * 64;
    cx.nw   = (cx.wid & 3) * 32;

    #pragma unroll
    for (int i = 0; i < 4; i++) {
        int idx = i * 256 + tid;
        int row = idx >> 3;
        int seg = idx & 7;
        cx.rowoffA[i] = (row0 + row) * lda + seg * 8;
        cx.rowoffB[i] = (col0 + row) * ldb + seg * 8;
        cx.smoff[i]   = (uint32_t)(row * 128 + ((seg ^ (row & 7)) << 4));
    }
    int r  = cx.lane & 7;
    int q  = cx.lane >> 3;
    int ql = q & 1;
    int qh = q >> 1;
    #pragma unroll
    for (int ks = 0; ks < 4; ks++)
        cx.segoff[ks] = (uint32_t)((((2 * ks + qh) ^ r) << 4));
    cx.ArowB = sb + (uint32_t)((cx.mw + ql * 8 + r) * 128);
    cx.BrowB = sb + SM_BUF + (uint32_t)((cx.nw + ql * 8 + r) * 128);
}

// ---------------------------------------------------------------------------
// NT bf16 tensor-core GEMM (proj / transfer): CTA 128x128, 8 warps 64x32,
// 2 CTA/SM, 3-stage cp.async.
// mode 0: bf16 store of (acc+bias)  [dual-set via z=1]
// mode 3: fp32 Cls + Ifc*acc/rowsum[row]  (batched)
// ---------------------------------------------------------------------------
__global__ __launch_bounds__(256, 2)
void gemm_bf_kernel(const __nv_bfloat16* __restrict__ A,
                    const __nv_bfloat16* __restrict__ B,
                    const float* __restrict__ bias,
                    const float* __restrict__ Cls,
                    const float* __restrict__ Ifc,
                    void* __restrict__ Cout,
                    const __nv_bfloat16* __restrict__ Ad,
                    const __nv_bfloat16* __restrict__ Bd,
                    const float* __restrict__ biasd,
                    void* __restrict__ Cd,
                    const float* __restrict__ rowsum,
                    int N, int K, int lda,
                    long As_batch, long Bs_batch, long Cs_batch,
                    int mode)
{
    extern __shared__ char smem[];
    uint32_t sb = smem_u32(smem);

    int bz = blockIdx.z;
    if (Ad && bz == 1) {
        A = Ad; B = Bd; bias = biasd; Cout = Cd;
        bz = 0;
    }
    A += bz * As_batch;
    B += bz * Bs_batch;
    if (Cls) Cls += bz * Cs_batch;
    if (Ifc) Ifc += bz * Cs_batch;
    const float* rs = rowsum ? (rowsum + bz * SS) : nullptr;

    int row0 = blockIdx.y * 128;
    int col0 = blockIdx.x * 128;

    GemmCtx cx;
    gemm_setup(cx, sb, row0, col0, lda, K);

    float acc[4][4][4];
    #pragma unroll
    for (int i = 0; i < 4; i++)
        #pragma unroll
        for (int j = 0; j < 4; j++)
            #pragma unroll
            for (int p = 0; p < 4; p++) acc[i][j][p] = 0.0f;

    const int NC = K / KC;
    #pragma unroll
    for (int p = 0; p < 2; p++) {
        int kt = p * KC;
        issue_chunk(A + kt, B + kt, cx.rowoffA, cx.rowoffB, cx.smoff, sb + p * SM_STAGE);
    }

    int stage = 0;
    for (int ch = 0; ch < NC; ch++) {
        if (ch + 1 < NC) { CP_WAIT(1); } else { CP_WAIT(0); }
        __syncthreads();

        uint32_t At = cx.ArowB + stage * SM_STAGE;
        uint32_t Bt = cx.BrowB + stage * SM_STAGE;

        #pragma unroll
        for (int ks = 0; ks < 4; ks++) {
            uint32_t so = cx.segoff[ks];
            uint32_t af[4][4];
            #pragma unroll
            for (int i = 0; i < 4; i++)
                LDSM4(af[i], At + i * 2048 + so);
            uint32_t bf[4][2];
            #pragma unroll
            for (int j2 = 0; j2 < 2; j2++) {
                uint32_t t[4];
                LDSM4(t, Bt + j2 * 2048 + so);
                bf[2 * j2][0]     = t[0];
                bf[2 * j2 + 1][0] = t[1];
                bf[2 * j2][1]     = t[2];
                bf[2 * j2 + 1][1] = t[3];
            }
            #pragma unroll
            for (int i = 0; i < 4; i++)
                #pragma unroll
                for (int j = 0; j < 4; j++)
                    mma16(acc[i][j], af[i], bf[j]);
        }

        if (ch + 2 < NC) {
            int kt = (ch + 2) * KC;
            int ns = stage + 2; if (ns >= NSTAGE) ns -= NSTAGE;
            issue_chunk(A + kt, B + kt, cx.rowoffA, cx.rowoffB, cx.smoff, sb + ns * SM_STAGE);
        }
        stage++; if (stage >= NSTAGE) stage = 0;
    }

    #pragma unroll
    for (int i = 0; i < 4; i++) {
        int rA = row0 + cx.mw + 16 * i + cx.g;
        int rB = rA + 8;
        float invA = 0.0f, invB = 0.0f;
        if (mode == 3) {
            invA = 1.0f / rs[rA];
            invB = 1.0f / rs[rB];
        }
        #pragma unroll
        for (int j = 0; j < 4; j++) {
            int c = col0 + cx.nw + 8 * j + 2 * cx.tig;
            float2 v0 = make_float2(acc[i][j][0], acc[i][j][1]);
            float2 v1 = make_float2(acc[i][j][2], acc[i][j][3]);

            if (mode == 0) {
                float2 bb = *reinterpret_cast<const float2*>(bias + c);
                __nv_bfloat16* Cb = (__nv_bfloat16*)Cout;
                *reinterpret_cast<uint32_t*>(Cb + (long)rA * N + c) =
                    pack_bf16(v0.x + bb.x, v0.y + bb.y);
                *reinterpret_cast<uint32_t*>(Cb + (long)rB * N + c) =
                    pack_bf16(v1.x + bb.x, v1.y + bb.y);
            } else {
                float* Cf = (float*)Cout + bz * Cs_batch;
                long i0 = (long)rA * N + c;
                long i1 = (long)rB * N + c;
                float2 cl0 = *reinterpret_cast<const float2*>(Cls + i0);
                float2 cl1 = *reinterpret_cast<const float2*>(Cls + i1);
                float2 fi0 = *reinterpret_cast<const float2*>(Ifc + i0);
                float2 fi1 = *reinterpret_cast<const float2*>(Ifc + i1);
                v0.x = cl0.x + fi0.x * v0.x * invA;  v0.y = cl0.y + fi0.y * v0.y * invA;
                v1.x = cl1.x + fi1.x * v1.x * invB;  v1.y = cl1.y + fi1.y * v1.y * invB;
                *reinterpret_cast<float2*>(Cf + i0) = v0;
                *reinterpret_cast<float2*>(Cf + i1) = v1;
            }
        }
    }
}

// ---------------------------------------------------------------------------
// Fused gating + sim + transpose launch. grid = (16,16,7).
//   z in {0,1}: gating -> iface = sigmoid([cproj|qproj] @ Wg^T + bg)  (fp32)
//   z in {2..5}: sim batch (z-2) -> attn = bf16(exp(sim*s - 6)), rowsum += sums
//   z == 6: transpose quantum fp32 [S,D] -> bf16 qT [D,S] (256 CTAs x 32 tiles)
// Gating CTAs (2x work) dispatch first; transpose backfills the tail.
// ---------------------------------------------------------------------------
__global__ __launch_bounds__(256, 2)
void gemm_fused_kernel(const __nv_bfloat16* __restrict__ cproj,
                       const __nv_bfloat16* __restrict__ qproj,
                       const __nv_bfloat16* __restrict__ Wg,
                       const float* __restrict__ bg,
                       float* __restrict__ iface,
                       __nv_bfloat16* __restrict__ attn,
                       const float* __restrict__ temp,
                       float* __restrict__ rowsum,
                       const float* __restrict__ tr_in,
                       __nv_bfloat16* __restrict__ tr_out)
{
    extern __shared__ char smem[];
    uint32_t sb = smem_u32(smem);

    int z = blockIdx.z;

    // ---- transpose plane ----
    if (z == 6) {
        float (*t)[33] = reinterpret_cast<float(*)[33]>(smem);
        int tx = threadIdx.x & 31;
        int ty = threadIdx.x >> 5;   // 0..7
        int flat = blockIdx.y * 16 + blockIdx.x;         // 0..255
        for (int it = 0; it < 32; it++) {
            int tile = flat * 32 + it;                   // 0..8191
            int b    = tile >> 11;                       // 2048 tiles/batch
            int rem  = tile & 2047;
            int d0   = (rem & 31) * 32;
            int s0   = (rem >> 5) * 32;
            const float* in = tr_in + (long)b * SS * DD;
            __nv_bfloat16* out = tr_out + (long)b * DD * SS;
            #pragma unroll
            for (int i = 0; i < 4; i++) {
                int s = s0 + ty + i * 8;
                t[ty + i * 8][tx] = in[(long)s * DD + d0 + tx];
            }
            __syncthreads();
            #pragma unroll
            for (int i = 0; i < 4; i++) {
                int d = d0 + ty + i * 8;
                out[(long)d * SS + s0 + tx] = __float2bfloat16(t[tx][ty + i * 8]);
            }
            __syncthreads();
        }
        return;
    }

    const __nv_bfloat16 *A, *A2, *B;
    int row0, col0, N, K, Ksplit, ldb;
    bool gating;
    long rowbase = 0;

    if (z < 2) {
        gating = true;
        int flat = z * 256 + blockIdx.y * 16 + blockIdx.x;   // 0..511
        row0 = (flat >> 3) * 128;
        col0 = (flat & 7) * 128;
        A = cproj; A2 = qproj; B = Wg;
        N = DD; K = 2 * DD; Ksplit = DD; ldb = 2 * DD;
    } else {
        gating = false;
        int bz = z - 2;
        row0 = blockIdx.y * 128;
        col0 = blockIdx.x * 128;
        A = cproj + (long)bz * SS * DD; A2 = A;
        B = qproj + (long)bz * SS * DD;
        attn += (long)bz * SS * SS;
        rowbase = (long)bz * SS;
        N = SS; K = DD; Ksplit = DD; ldb = DD;
    }

    GemmCtx cx;
    gemm_setup(cx, sb, row0, col0, DD, ldb);

    float acc[4][4][4];
    #pragma unroll
    for (int i = 0; i < 4; i++)
        #pragma unroll
        for (int j = 0; j < 4; j++)
            #pragma unroll
            for (int p = 0; p < 4; p++) acc[i][j][p] = 0.0f;

    const int NC = K / KC;
    #pragma unroll
    for (int p = 0; p < 2; p++) {
        int kt = p * KC;
        const __nv_bfloat16* bA = (kt < Ksplit) ? (A + kt) : (A2 + (kt - Ksplit));
        issue_chunk(bA, B + kt, cx.rowoffA, cx.rowoffB, cx.smoff, sb + p * SM_STAGE);
    }

    int stage = 0;
    for (int ch = 0; ch < NC; ch++) {
        if (ch + 1 < NC) { CP_WAIT(1); } else { CP_WAIT(0); }
        __syncthreads();

        uint32_t At = cx.ArowB + stage * SM_STAGE;
        uint32_t Bt = cx.BrowB + stage * SM_STAGE;

        #pragma unroll
        for (int ks = 0; ks < 4; ks++) {
            uint32_t so = cx.segoff[ks];
            uint32_t af[4][4];
            #pragma unroll
            for (int i = 0; i < 4; i++)
                LDSM4(af[i], At + i * 2048 + so);
            uint32_t bf[4][2];
            #pragma unroll
            for (int j2 = 0; j2 < 2; j2++) {
                uint32_t t[4];
                LDSM4(t, Bt + j2 * 2048 + so);
                bf[2 * j2][0]     = t[0];
                bf[2 * j2 + 1][0] = t[1];
                bf[2 * j2][1]     = t[2];
                bf[2 * j2 + 1][1] = t[3];
            }
            #pragma unroll
            for (int i = 0; i < 4; i++)
                #pragma unroll
                for (int j = 0; j < 4; j++)
                    mma16(acc[i][j], af[i], bf[j]);
        }

        if (ch + 2 < NC) {
            int kt = (ch + 2) * KC;
            const __nv_bfloat16* bA = (kt < Ksplit) ? (A + kt) : (A2 + (kt - Ksplit));
            int ns = stage + 2; if (ns >= NSTAGE) ns -= NSTAGE;
            issue_chunk(bA, B + kt, cx.rowoffA, cx.rowoffB, cx.smoff, sb + ns * SM_STAGE);
        }
        stage++; if (stage >= NSTAGE) stage = 0;
    }

    if (gating) {
        #pragma unroll
        for (int i = 0; i < 4; i++) {
            int rA = row0 + cx.mw + 16 * i + cx.g;
            int rB = rA + 8;
            #pragma unroll
            for (int j = 0; j < 4; j++) {
                int c = col0 + cx.nw + 8 * j + 2 * cx.tig;
                float2 bb = *reinterpret_cast<const float2*>(bg + c);
                float2 v0, v1;
                v0.x = 1.0f / (1.0f + __expf(-(acc[i][j][0] + bb.x)));
                v0.y = 1.0f / (1.0f + __expf(-(acc[i][j][1] + bb.y)));
                v1.x = 1.0f / (1.0f + __expf(-(acc[i][j][2] + bb.x)));
                v1.y = 1.0f / (1.0f + __expf(-(acc[i][j][3] + bb.y)));
                *reinterpret_cast<float2*>(iface + (long)rA * N + c) = v0;
                *reinterpret_cast<float2*>(iface + (long)rB * N + c) = v1;
            }
        }
    } else {
        float sc = (1.0f / 32.0f) / (*temp);
        #pragma unroll
        for (int i = 0; i < 4; i++) {
            int rA = row0 + cx.mw + 16 * i + cx.g;
            int rB = rA + 8;
            float sumA = 0.0f, sumB = 0.0f;
            #pragma unroll
            for (int j = 0; j < 4; j++) {
                int c = col0 + cx.nw + 8 * j + 2 * cx.tig;
                float e0 = __expf(acc[i][j][0] * sc - EXP_BIAS);
                float e1 = __expf(acc[i][j][1] * sc - EXP_BIAS);
                float e2 = __expf(acc[i][j][2] * sc - EXP_BIAS);
                float e3 = __expf(acc[i][j][3] * sc - EXP_BIAS);
                sumA += e0 + e1;
                sumB += e2 + e3;
                *reinterpret_cast<uint32_t*>(attn + (long)rA * N + c) = pack_bf16(e0, e1);
                *reinterpret_cast<uint32_t*>(attn + (long)rB * N + c) = pack_bf16(e2, e3);
            }
            sumA += __shfl_xor_sync(0xffffffffu, sumA, 1);
            sumA += __shfl_xor_sync(0xffffffffu, sumA, 2);
            sumB += __shfl_xor_sync(0xffffffffu, sumB, 1);
            sumB += __shfl_xor_sync(0xffffffffu, sumB, 2);
            if (cx.tig == 0) {
                atomicAdd(rowsum + rowbase + rA, sumA);
                atomicAdd(rowsum + rowbase + rB, sumB);
            }
        }
    }
}

// ---------------------------------------------------------------------------
// Fused fp32 -> bf16 conversion of all five inputs (1 float4/thread).
// Also zeroes g_rowsum (first MS/4 threads).
// ---------------------------------------------------------------------------
#define N4_CLS ((long)MS*DD/4)
#define N4_W   ((long)DD*DD/4)
#define N4_WG  ((long)DD*2*DD/4)
#define N4_TOTAL (2*N4_CLS + 2*N4_W + N4_WG)
__global__ __launch_bounds__(256)
void tobf16_all_kernel(const float* __restrict__ cls, const float* __restrict__ q,
                       const float* __restrict__ Wc, const float* __restrict__ Wq,
                       const float* __restrict__ Wg,
                       __nv_bfloat16* __restrict__ cls_o, __nv_bfloat16* __restrict__ q_o,
                       __nv_bfloat16* __restrict__ Wc_o, __nv_bfloat16* __restrict__ Wq_o,
                       __nv_bfloat16* __restrict__ Wg_o,
                       float* __restrict__ rowsum)
{
    long i = (long)blockIdx.x * 256 + threadIdx.x;
    if (i < MS / 4)
        reinterpret_cast<float4*>(rowsum)[i] = make_float4(0.f, 0.f, 0.f, 0.f);
    const float* src; __nv_bfloat16* dst; long off;
    if (i < N4_CLS)                        { src = cls; dst = cls_o; off = i; }
    else if (i < 2 * N4_CLS)               { src = q;   dst = q_o;   off = i - N4_CLS; }
    else if (i < 2 * N4_CLS + N4_W)        { src = Wc;  dst = Wc_o;  off = i - 2 * N4_CLS; }
    else if (i < 2 * N4_CLS + 2 * N4_W)    { src = Wq;  dst = Wq_o;  off = i - 2 * N4_CLS - N4_W; }
    else                                   { src = Wg;  dst = Wg_o;  off = i - 2 * N4_CLS - 2 * N4_W; }
    float4 v = reinterpret_cast<const float4*>(src)[off];
    uint2 o;
    o.x = pack_bf16(v.x, v.y);
    o.y = pack_bf16(v.z, v.w);
    reinterpret_cast<uint2*>(dst)[off] = o;
}

// ---------------------------------------------------------------------------
extern "C" void kernel_launch(void* const* d_in, const int* in_sizes, int n_in,
                              void* d_out, int out_size)
{
    const float* classical = (const float*)d_in[0];
    const float* quantum   = (const float*)d_in[1];
    const float* Wc        = (const float*)d_in[2];
    const float* bc        = (const float*)d_in[3];
    const float* Wq        = (const float*)d_in[4];
    const float* bq        = (const float*)d_in[5];
    const float* Wg        = (const float*)d_in[6];
    const float* bg        = (const float*)d_in[7];
    const float* temp      = (const float*)d_in[8];
    float* out             = (float*)d_out;

    __nv_bfloat16 *cls_bf, *q_bf, *Wc_bf, *Wq_bf, *Wg_bf, *cproj, *qproj, *qT, *attn;
    float *iface, *rowsum;
    cudaGetSymbolAddress((void**)&cls_bf, g_cls_bf);
    cudaGetSymbolAddress((void**)&q_bf,   g_q_bf);
    cudaGetSymbolAddress((void**)&Wc_bf,  g_Wc_bf);
    cudaGetSymbolAddress((void**)&Wq_bf,  g_Wq_bf);
    cudaGetSymbolAddress((void**)&Wg_bf,  g_Wg_bf);
    cudaGetSymbolAddress((void**)&cproj,  g_cproj);
    cudaGetSymbolAddress((void**)&qproj,  g_qproj);
    cudaGetSymbolAddress((void**)&qT,     g_qT);
    cudaGetSymbolAddress((void**)&attn,   g_attn);
    cudaGetSymbolAddress((void**)&iface,  g_iface);
    cudaGetSymbolAddress((void**)&rowsum, g_rowsum);

    cudaFuncSetAttribute(gemm_bf_kernel,
                         cudaFuncAttributeMaxDynamicSharedMemorySize, SM_TOTAL);
    cudaFuncSetAttribute(gemm_fused_kernel,
                         cudaFuncAttributeMaxDynamicSharedMemorySize, SM_TOTAL);

    dim3 blk(256);

    // Convert all inputs to bf16 + zero rowsum (single launch)
    tobf16_all_kernel<<<(unsigned)(N4_TOTAL/256), 256>>>(
        classical, quantum, Wc, Wq, Wg,
        cls_bf, q_bf, Wc_bf, Wq_bf, Wg_bf, rowsum);

    // 1+2) fused dual projection:
    //   z=0: cproj = bf16(classical @ Wc^T + bc)
    //   z=1: qproj = bf16(quantum   @ Wq^T + bq)
    gemm_bf_kernel<<<dim3(DD/128, MS/128, 2), blk, SM_TOTAL>>>(
        cls_bf, Wc_bf, bc, nullptr, nullptr, cproj,
        q_bf, Wq_bf, bq, qproj,
        nullptr,
        DD, DD, DD, 0, 0, 0, 0);

    // 3+4+softmax-exp+transpose) fused launch:
    //   z 0-1: gating -> iface (fp32 sigmoid)
    //   z 2-5: sim    -> attn = bf16(exp(sim*s - 6)), rowsum atomic
    //   z 6  : qT[b] = bf16(quantum[b]^T)  (tail backfill, no proj dependency)
    gemm_fused_kernel<<<dim3(16, 16, 7), blk, SM_TOTAL>>>(
        cproj, qproj, Wg_bf, bg, iface, attn, temp, rowsum,
        quantum, qT);

    // 5) out = classical + iface * (attn[b] @ qT[b]^T) / rowsum
    gemm_bf_kernel<<<dim3(DD/128, SS/128, BB), blk, SM_TOTAL>>>(
        attn, qT, nullptr, classical, iface, out,
        nullptr, nullptr, nullptr, nullptr,
        rowsum,
        DD, SS, SS,
        (long)SS*SS, (long)DD*SS, (long)SS*DD, 3);
}